// round 4
// baseline (speedup 1.0000x reference)
#include <cuda_runtime.h>
#include <cuda_bf16.h>
#include <cstdint>

// Problem constants
#define F_ 32
#define B_ 4096
#define D_ 64
#define K_ 512

#define NTHREADS 256
typedef unsigned long long ull;

// ---------------- device scratch (no allocs allowed) ----------------
__device__ float g_wt [(size_t)F_ * K_ * D_];  // exact codebook [f][k][d] (gather)
__device__ float g_whi[(size_t)F_ * D_ * K_];  // tf32 hi, native [f][d][k]
__device__ float g_wlo[(size_t)F_ * D_ * K_];  // tf32 lo, native [f][d][k]
__device__ float g_wn [F_ * K_];               // 0.5*||w_k||^2
__device__ float g_partial[2048];

#define CVT_TF32(u_, f_) asm("cvt.rna.tf32.f32 %0, %1;" : "=r"(u_) : "f"(f_))

__device__ __forceinline__ void mma_tf32(float* c, const uint32_t* a,
                                         const uint32_t* b) {
    asm volatile(
        "mma.sync.aligned.m16n8k8.row.col.f32.tf32.tf32.f32 "
        "{%0,%1,%2,%3}, {%4,%5,%6,%7}, {%8,%9}, {%0,%1,%2,%3};"
        : "+f"(c[0]), "+f"(c[1]), "+f"(c[2]), "+f"(c[3])
        : "r"(a[0]), "r"(a[1]), "r"(a[2]), "r"(a[3]), "r"(b[0]), "r"(b[1]));
}

// smem layout (bytes):
//   0      wns[512] floats (2048)
//   2048   sidx[128] ints  (512)
//   2560   red8[8] floats
//   4096   xs_hi  128 x 68 floats (34816)
//   38912  xs_lo
//   73728  ws_hi  64 x 136 floats (34816)   } overlay: red_v[2048]f, red_i[2048]i
//   108544 ws_lo
#define XS_STRIDE 68
#define WS_STRIDE 136
#define OFF_WNS   0
#define OFF_SIDX  2048
#define OFF_RED8  2560
#define OFF_XHI   4096
#define OFF_XLO   38912
#define OFF_WHI   73728
#define OFF_WLO   108544
#define SMEM_BYTES 143360

// ---------------------------------------------------------------------------
// Prep: elementwise tf32 split (native layout) + transposed copy + norms
// grid (8, 32) x 256: block handles f = blockIdx.y, codes kt*64..+64
// ---------------------------------------------------------------------------
__global__ void vq_prep(const float* __restrict__ w) {
    __shared__ float ts[64][65];
    const int f = blockIdx.y, kt = blockIdx.x, tid = threadIdx.x;
    const size_t fbase = (size_t)f * D_ * K_;
    const float* wf = w + fbase + kt * 64;

    for (int i = tid; i < 64 * 64; i += 256) {
        int d = i >> 6, kk = i & 63;
        float v = wf[(size_t)d * K_ + kk];        // coalesced along k
        ts[kk][d] = v;
        uint32_t uh; CVT_TF32(uh, v);
        float hi = __uint_as_float(uh);
        float l = v - hi;
        uint32_t ul; CVT_TF32(ul, l);
        size_t gi = fbase + (size_t)d * K_ + kt * 64 + kk;
        g_whi[gi] = hi;
        g_wlo[gi] = __uint_as_float(ul);
    }
    __syncthreads();

    float* wt = g_wt + ((size_t)f * K_ + (size_t)kt * 64) * D_;
    for (int i = tid; i < 64 * 64; i += 256) {
        int kk = i >> 6, d = i & 63;
        wt[i] = ts[kk][d];                         // coalesced along d
    }
    if (tid < 64) {
        float s = 0.f;
#pragma unroll
        for (int d = 0; d < 64; ++d) { float v = ts[tid][d]; s += v * v; }
        g_wn[f * K_ + kt * 64 + tid] = 0.5f * s;
    }
}

// ---------------------------------------------------------------------------
// Main: mma.sync tf32 3x-split distance GEMM + fused argmax + gather + loss
// grid (32, 32): x = 128-row tile, y = f. 256 threads = 8 warps (2M x 4N).
// ---------------------------------------------------------------------------
__global__ __launch_bounds__(NTHREADS, 1)
void vq_main(const float* __restrict__ x, float* __restrict__ out) {
    extern __shared__ __align__(16) char smem[];
    float* wns   = (float*)(smem + OFF_WNS);
    int*   sidx  = (int*)(smem + OFF_SIDX);
    float* red8  = (float*)(smem + OFF_RED8);
    float* xs_hi = (float*)(smem + OFF_XHI);
    float* xs_lo = (float*)(smem + OFF_XLO);
    float* ws_hi = (float*)(smem + OFF_WHI);
    float* ws_lo = (float*)(smem + OFF_WLO);
    float* red_v = ws_hi;                   // overlay after GEMM
    int*   red_i = (int*)(ws_hi + 2048);

    const int f   = blockIdx.y;
    const int b0  = blockIdx.x * 128;
    const int tid = threadIdx.x;
    const int wid = tid >> 5;
    const int lane = tid & 31;
    const int tq = lane >> 2;     // 0..7
    const int tr = lane & 3;      // 0..3
    const int wm = wid >> 2;      // 0..1 -> rows wm*64..
    const int wn = wid & 3;       // 0..3 -> cols wn*32..

    // wns
    wns[tid]       = g_wn[(f << 9) + tid];
    wns[tid + 256] = g_wn[(f << 9) + tid + 256];

    // ---- load x tile, tf32 split, store [row][d] (stride 68) ----
    const float* xg = x + ((size_t)f * B_ + b0) * D_;
    for (int i = tid; i < 2048; i += NTHREADS) {      // 128 rows x 16 float4
        int r  = i >> 4;
        int c4 = i & 15;
        float4 v = ((const float4*)(xg + (size_t)r * D_))[c4];
        float vv[4] = {v.x, v.y, v.z, v.w};
        float hi[4], lo[4];
#pragma unroll
        for (int j = 0; j < 4; ++j) {
            uint32_t uh; CVT_TF32(uh, vv[j]);
            hi[j] = __uint_as_float(uh);
            float l = vv[j] - hi[j];
            uint32_t ul; CVT_TF32(ul, l);
            lo[j] = __uint_as_float(ul);
        }
        float* ph = xs_hi + r * XS_STRIDE + c4 * 4;
        float* pl = xs_lo + r * XS_STRIDE + c4 * 4;
        *(float4*)ph = make_float4(hi[0], hi[1], hi[2], hi[3]);
        *(float4*)pl = make_float4(lo[0], lo[1], lo[2], lo[3]);
    }

    float best[8];
    int   bidx[8];
#pragma unroll
    for (int i = 0; i < 8; ++i) { best[i] = -1e30f; bidx[i] = 0; }

    const float* whig = g_whi + (size_t)f * D_ * K_;
    const float* wlog = g_wlo + (size_t)f * D_ * K_;

    for (int c = 0; c < 4; ++c) {
        __syncthreads();   // ws free / x stores visible
        // load w chunk: ws[d][n] = w[f][d][c*128+n], both hi & lo
        for (int i = tid; i < 2048; i += NTHREADS) {  // 64 d x 32 float4
            int d  = i >> 5;
            int c4 = i & 31;
            size_t gi = (size_t)d * K_ + c * 128 + c4 * 4;
            *(float4*)(ws_hi + d * WS_STRIDE + c4 * 4) = *(const float4*)(whig + gi);
            *(float4*)(ws_lo + d * WS_STRIDE + c4 * 4) = *(const float4*)(wlog + gi);
        }
        __syncthreads();

        float acc[4][4][4];
#pragma unroll
        for (int i = 0; i < 4; ++i)
#pragma unroll
            for (int j = 0; j < 4; ++j)
#pragma unroll
                for (int q = 0; q < 4; ++q) acc[i][j][q] = 0.f;

#pragma unroll
        for (int kk = 0; kk < 8; ++kk) {
            const int kb = kk * 8;
            uint32_t ah[4][4], al[4][4], bh[4][2], bl[4][2];
#pragma unroll
            for (int i = 0; i < 4; ++i) {
                int r0 = wm * 64 + i * 16 + tq;
                const float* ph = xs_hi + r0 * XS_STRIDE + kb + tr;
                const float* pl = xs_lo + r0 * XS_STRIDE + kb + tr;
                ah[i][0] = __float_as_uint(ph[0]);
                ah[i][1] = __float_as_uint(ph[8 * XS_STRIDE]);
                ah[i][2] = __float_as_uint(ph[4]);
                ah[i][3] = __float_as_uint(ph[8 * XS_STRIDE + 4]);
                al[i][0] = __float_as_uint(pl[0]);
                al[i][1] = __float_as_uint(pl[8 * XS_STRIDE]);
                al[i][2] = __float_as_uint(pl[4]);
                al[i][3] = __float_as_uint(pl[8 * XS_STRIDE + 4]);
            }
#pragma unroll
            for (int j = 0; j < 4; ++j) {
                int n0 = wn * 32 + j * 8 + tq;
                const float* ph = ws_hi + (kb + tr) * WS_STRIDE + n0;
                const float* pl = ws_lo + (kb + tr) * WS_STRIDE + n0;
                bh[j][0] = __float_as_uint(ph[0]);
                bh[j][1] = __float_as_uint(ph[4 * WS_STRIDE]);
                bl[j][0] = __float_as_uint(pl[0]);
                bl[j][1] = __float_as_uint(pl[4 * WS_STRIDE]);
            }
#pragma unroll
            for (int i = 0; i < 4; ++i)
#pragma unroll
                for (int j = 0; j < 4; ++j) {
                    mma_tf32(acc[i][j], ah[i], bh[j]);   // hi*hi
                    mma_tf32(acc[i][j], ah[i], bl[j]);   // hi*lo
                    mma_tf32(acc[i][j], al[i], bh[j]);   // lo*hi
                }
        }

        // fold chunk scores into running argmax (k ascending within thread)
#pragma unroll
        for (int j = 0; j < 4; ++j)
#pragma unroll
            for (int c01 = 0; c01 < 2; ++c01) {
                int kg = c * 128 + wn * 32 + j * 8 + tr * 2 + c01;
                float wnv = wns[kg];
#pragma unroll
                for (int i = 0; i < 4; ++i)
#pragma unroll
                    for (int h = 0; h < 2; ++h) {
                        float s = acc[i][j][h * 2 + c01] - wnv;
                        int slot = i * 2 + h;
                        if (s > best[slot]) { best[slot] = s; bidx[slot] = kg; }
                    }
            }
    }

    __syncthreads();   // ws reads done; overlay reduction arrays

    // per-row candidates: 16 = 4 (tr) x 4 (wn)
#pragma unroll
    for (int i = 0; i < 4; ++i)
#pragma unroll
        for (int h = 0; h < 2; ++h) {
            int row = wm * 64 + i * 16 + h * 8 + tq;
            red_v[row * 16 + wn * 4 + tr] = best[i * 2 + h];
            red_i[row * 16 + wn * 4 + tr] = bidx[i * 2 + h];
        }
    __syncthreads();

    if (tid < 128) {
        float bv = -1e30f;
        int bk = 0x7FFFFFFF;
#pragma unroll
        for (int t = 0; t < 16; ++t) {
            float v = red_v[tid * 16 + t];
            int  kk = red_i[tid * 16 + t];
            if (v > bv || (v == bv && kk < bk)) { bv = v; bk = kk; }
        }
        sidx[tid] = bk;
    }
    __syncthreads();

    // ---- gather quantized rows, write out, loss partial ----
    float lsum = 0.f;
    float* og = out + ((size_t)f * B_ + b0) * D_;
    const float* wtf = g_wt + ((size_t)f << 9) * D_;
    for (int e = tid; e < 128 * D_; e += NTHREADS) {
        int r = e >> 6, d = e & 63;
        float q  = wtf[(size_t)sidx[r] * D_ + d];
        float xv = xg[e];
        og[e] = q;
        float dif = q - xv;
        lsum += dif * dif;
    }
#pragma unroll
    for (int o = 16; o > 0; o >>= 1)
        lsum += __shfl_xor_sync(0xFFFFFFFFu, lsum, o);
    if ((tid & 31) == 0) red8[wid] = lsum;
    __syncthreads();
    if (tid == 0) {
        float t = 0.f;
#pragma unroll
        for (int i = 0; i < 8; ++i) t += red8[i];
        g_partial[blockIdx.y * gridDim.x + blockIdx.x] = t;
    }
}

// ---------------------------------------------------------------------------
__global__ void vq_final(float* __restrict__ out, int nblocks, int loss_pos) {
    __shared__ float sm[8];
    int tid = threadIdx.x;
    float s = 0.f;
    for (int i = tid; i < nblocks; i += 256) s += g_partial[i];
#pragma unroll
    for (int o = 16; o > 0; o >>= 1)
        s += __shfl_xor_sync(0xFFFFFFFFu, s, o);
    if ((tid & 31) == 0) sm[tid >> 5] = s;
    __syncthreads();
    if (tid == 0) {
        float t = 0.f;
        for (int i = 0; i < 8; ++i) t += sm[i];
        out[loss_pos] = t * (1.25f / (float)(F_ * B_ * D_));
    }
}

// ---------------------------------------------------------------------------
extern "C" void kernel_launch(void* const* d_in, const int* in_sizes, int n_in,
                              void* d_out, int out_size) {
    const float* x = (const float*)d_in[0];   // (F,B,D)
    const float* w = (const float*)d_in[1];   // (F,D,K)
    float* out = (float*)d_out;

    cudaFuncSetAttribute(vq_main, cudaFuncAttributeMaxDynamicSharedMemorySize,
                         SMEM_BYTES);

    dim3 pgrid(8, 32);
    vq_prep<<<pgrid, 256>>>(w);

    dim3 grid(B_ / 128, F_);
    vq_main<<<grid, NTHREADS, SMEM_BYTES>>>(x, out);

    vq_final<<<1, 256>>>(out, 1024, out_size - 1);
}

// round 5
// speedup vs baseline: 1.7275x; 1.7275x over previous
#include <cuda_runtime.h>
#include <cuda_fp16.h>
#include <cstdint>

#define F_ 32
#define B_ 4096
#define D_ 64
#define K_ 512
#define NTHREADS 256
typedef unsigned long long ull;

// ---------------- device scratch ----------------
__device__ float  g_wt [(size_t)F_ * K_ * D_];  // exact codebook [f][k][d]
__device__ __half g_wh1[(size_t)F_ * K_ * D_];  // fp16 limb1, [f][k][d]
__device__ __half g_wh2[(size_t)F_ * K_ * D_];  // fp16 limb2, [f][k][d]
__device__ float  g_wn [F_ * K_];               // 0.5*||w_k||^2
__device__ float  g_partial[2048];

__device__ __forceinline__ uint32_t smem_u32(const void* p) {
    uint32_t a;
    asm("{ .reg .u64 t; cvta.to.shared.u64 t, %1; cvt.u32.u64 %0, t; }"
        : "=r"(a) : "l"(p));
    return a;
}

#define LDSM_X4(r_, addr_) \
    asm volatile("ldmatrix.sync.aligned.m8n8.x4.shared.b16 {%0,%1,%2,%3}, [%4];" \
        : "=r"((r_)[0]), "=r"((r_)[1]), "=r"((r_)[2]), "=r"((r_)[3]) : "r"(addr_))

__device__ __forceinline__ void mma_f16(float* c, const uint32_t* a,
                                        const uint32_t* b) {
    asm volatile(
        "mma.sync.aligned.m16n8k16.row.col.f32.f16.f16.f32 "
        "{%0,%1,%2,%3}, {%4,%5,%6,%7}, {%8,%9}, {%0,%1,%2,%3};"
        : "+f"(c[0]), "+f"(c[1]), "+f"(c[2]), "+f"(c[3])
        : "r"(a[0]), "r"(a[1]), "r"(a[2]), "r"(a[3]), "r"(b[0]), "r"(b[1]));
}

__device__ __forceinline__ uint32_t pack_h2(__half a, __half b) {
    __half2 h = __halves2half2(a, b);
    return *(uint32_t*)&h;
}

// smem layout (bytes). stride = 72 halves = 144 B (16B-aligned rows).
//   0      wns[512] f32 (2048)
//   2048   sidx[128] int (512)
//   2560   red8[8] f32
//   4096   xs1  128 x 72 halves (18432)
//   22528  xs2
//   40960  ws1  128 x 72 halves   } overlay: red_v[2048]f @40960, red_i @49152
//   59392  ws2
#define STRD 72
#define OFF_WNS  0
#define OFF_SIDX 2048
#define OFF_RED8 2560
#define OFF_X1   4096
#define OFF_X2   22528
#define OFF_W1   40960
#define OFF_W2   59392
#define LIMB_DELTA 18432
#define SMEM_BYTES 77824

// ---------------------------------------------------------------------------
// Prep: transpose + fp16 2-limb split + norms.  grid (8, 32) x 256.
// ---------------------------------------------------------------------------
__global__ void vq_prep(const float* __restrict__ w) {
    __shared__ float ts[64][65];
    const int f = blockIdx.y, kt = blockIdx.x, tid = threadIdx.x;
    const float* wf = w + (size_t)f * D_ * K_ + kt * 64;

    for (int i = tid; i < 64 * 64; i += 256) {
        int d = i >> 6, kk = i & 63;
        ts[kk][d] = wf[(size_t)d * K_ + kk];          // coalesced along k
    }
    __syncthreads();

    size_t base = ((size_t)f * K_ + (size_t)kt * 64) * D_;
    for (int i = tid; i < 64 * 64; i += 256) {
        int kk = i >> 6, d = i & 63;
        float v = ts[kk][d];
        __half h1 = __float2half_rn(v);
        __half h2 = __float2half_rn(v - __half2float(h1));
        g_wt [base + i] = v;
        g_wh1[base + i] = h1;
        g_wh2[base + i] = h2;
    }
    if (tid < 64) {
        float s = 0.f;
#pragma unroll
        for (int d = 0; d < 64; ++d) { float v = ts[tid][d]; s += v * v; }
        g_wn[f * K_ + kt * 64 + tid] = 0.5f * s;
    }
}

// ---------------------------------------------------------------------------
// Main: fp16 2-limb (3-product) mma.sync GEMM + argmax + gather + loss.
// grid (32, 32). 256 thr = 8 warps (2M x 4N), warp tile 64x32, 4 N-chunks.
// ---------------------------------------------------------------------------
__global__ __launch_bounds__(NTHREADS, 2)
void vq_main(const float* __restrict__ x, float* __restrict__ out) {
    extern __shared__ __align__(16) char smem[];
    const uint32_t sb = smem_u32(smem);
    float* wns  = (float*)(smem + OFF_WNS);
    int*   sidx = (int*)(smem + OFF_SIDX);
    float* red8 = (float*)(smem + OFF_RED8);
    float* red_v = (float*)(smem + OFF_W1);
    int*   red_i = (int*)(smem + OFF_W1 + 8192);

    const int f   = blockIdx.y;
    const int b0  = blockIdx.x * 128;
    const int tid = threadIdx.x;
    const int wid = tid >> 5;
    const int lane = tid & 31;
    const int tq = lane >> 2, tr = lane & 3;
    const int wm = wid >> 2,  wn = wid & 3;
    const int lq = lane & 7,  quad = lane >> 3;

    wns[tid]       = g_wn[(f << 9) + tid];
    wns[tid + 256] = g_wn[(f << 9) + tid + 256];

    // ---- x tile -> fp16 limbs, [row][d] stride 72 ----
    const float* xg = x + ((size_t)f * B_ + b0) * D_;
    for (int i = tid; i < 2048; i += NTHREADS) {      // 128 rows x 16 float4
        int r = i >> 4, c4 = i & 15;
        float4 v = ((const float4*)(xg + (size_t)r * D_))[c4];
        float vv[4] = {v.x, v.y, v.z, v.w};
        __half h1[4], h2[4];
#pragma unroll
        for (int j = 0; j < 4; ++j) {
            h1[j] = __float2half_rn(vv[j]);
            h2[j] = __float2half_rn(vv[j] - __half2float(h1[j]));
        }
        uint32_t off = r * 144 + c4 * 8;              // bytes
        *(uint2*)(smem + OFF_X1 + off) =
            make_uint2(pack_h2(h1[0], h1[1]), pack_h2(h1[2], h1[3]));
        *(uint2*)(smem + OFF_X2 + off) =
            make_uint2(pack_h2(h2[0], h2[1]), pack_h2(h2[2], h2[3]));
    }

    // ldmatrix base addresses
    // A x4: m0 rows+0 cols+0 | m1 rows+8 | m2 cols+8 | m3 rows+8 cols+8
    const uint32_t aRow = (uint32_t)(wm * 64 + lq + ((quad & 1) << 3));
    const uint32_t aCol = (uint32_t)((quad >> 1) << 3);
    const uint32_t a_addr0 = sb + OFF_X1 + aRow * 144 + aCol * 2;
    // B x4: m0 n+0 d+0 | m1 n+0 d+8 | m2 d+16 | m3 d+24  (2 k-steps per x4)
    const uint32_t bRow = (uint32_t)(wn * 32 + lq);
    const uint32_t b_addr0 = sb + OFF_W1 + bRow * 144 + (uint32_t)quad * 16;

    float best[8];
    int   bidx[8];
#pragma unroll
    for (int i = 0; i < 8; ++i) { best[i] = -1e30f; bidx[i] = 0; }

    const __half* wh1g = g_wh1 + ((size_t)f << 9) * D_;
    const __half* wh2g = g_wh2 + ((size_t)f << 9) * D_;

    for (int c = 0; c < 4; ++c) {
        __syncthreads();
        // load ws limbs: 128 codes x 64 halves, row stride 72 halves
        for (int i = tid; i < 1024; i += NTHREADS) {
            int n = i >> 3, c8 = i & 7;
            size_t gi = ((size_t)(c * 128 + n)) * D_ + c8 * 8;
            uint32_t off = n * 144 + c8 * 16;
            *(uint4*)(smem + OFF_W1 + off) = *(const uint4*)(wh1g + gi);
            *(uint4*)(smem + OFF_W2 + off) = *(const uint4*)(wh2g + gi);
        }
        __syncthreads();

        float acc[4][4][4];
#pragma unroll
        for (int i = 0; i < 4; ++i)
#pragma unroll
            for (int j = 0; j < 4; ++j)
#pragma unroll
                for (int q = 0; q < 4; ++q) acc[i][j][q] = 0.f;

#pragma unroll
        for (int kkp = 0; kkp < 2; ++kkp) {
            uint32_t bb1[4][4], bb2[4][4];
#pragma unroll
            for (int j = 0; j < 4; ++j) {
                uint32_t ba = b_addr0 + (uint32_t)j * (8 * 144) + (uint32_t)kkp * 64;
                LDSM_X4(bb1[j], ba);
                LDSM_X4(bb2[j], ba + LIMB_DELTA);
            }
#pragma unroll
            for (int kk2 = 0; kk2 < 2; ++kk2) {
                const int kreg = kk2 * 2;
#pragma unroll
                for (int i = 0; i < 4; ++i) {
                    uint32_t aa = a_addr0 + (uint32_t)i * (16 * 144)
                                + (uint32_t)(kkp * 2 + kk2) * 32;
                    uint32_t a1[4], a2[4];
                    LDSM_X4(a1, aa);
                    LDSM_X4(a2, aa + LIMB_DELTA);
#pragma unroll
                    for (int j = 0; j < 4; ++j) {
                        mma_f16(acc[i][j], a1, &bb1[j][kreg]);  // h1*w1
                        mma_f16(acc[i][j], a1, &bb2[j][kreg]);  // h1*w2
                        mma_f16(acc[i][j], a2, &bb1[j][kreg]);  // h2*w1
                    }
                }
            }
        }

        // fold scores into running argmax (k ascending; strict >)
#pragma unroll
        for (int j = 0; j < 4; ++j)
#pragma unroll
            for (int c01 = 0; c01 < 2; ++c01) {
                int kg = c * 128 + wn * 32 + j * 8 + tr * 2 + c01;
                float wnv = wns[kg];
#pragma unroll
                for (int i = 0; i < 4; ++i)
#pragma unroll
                    for (int h = 0; h < 2; ++h) {
                        float s = acc[i][j][h * 2 + c01] - wnv;
                        int slot = i * 2 + h;
                        if (s > best[slot]) { best[slot] = s; bidx[slot] = kg; }
                    }
            }
    }

    __syncthreads();   // ws reads done; overlay reduction arrays

#pragma unroll
    for (int i = 0; i < 4; ++i)
#pragma unroll
        for (int h = 0; h < 2; ++h) {
            int row = wm * 64 + i * 16 + h * 8 + tq;
            red_v[row * 16 + wn * 4 + tr] = best[i * 2 + h];
            red_i[row * 16 + wn * 4 + tr] = bidx[i * 2 + h];
        }
    __syncthreads();

    if (tid < 128) {
        float bv = -1e30f;
        int bk = 0x7FFFFFFF;
#pragma unroll
        for (int t = 0; t < 16; ++t) {
            float v = red_v[tid * 16 + t];
            int  kk = red_i[tid * 16 + t];
            if (v > bv || (v == bv && kk < bk)) { bv = v; bk = kk; }
        }
        sidx[tid] = bk;
    }
    __syncthreads();

    // ---- gather + loss ----
    float lsum = 0.f;
    float* og = out + ((size_t)f * B_ + b0) * D_;
    const float* wtf = g_wt + ((size_t)f << 9) * D_;
    for (int e = tid; e < 128 * D_; e += NTHREADS) {
        int r = e >> 6, d = e & 63;
        float q  = wtf[(size_t)sidx[r] * D_ + d];
        float xv = xg[e];
        og[e] = q;
        float dif = q - xv;
        lsum += dif * dif;
    }
#pragma unroll
    for (int o = 16; o > 0; o >>= 1)
        lsum += __shfl_xor_sync(0xFFFFFFFFu, lsum, o);
    if ((tid & 31) == 0) red8[wid] = lsum;
    __syncthreads();
    if (tid == 0) {
        float t = 0.f;
#pragma unroll
        for (int i = 0; i < 8; ++i) t += red8[i];
        g_partial[blockIdx.y * gridDim.x + blockIdx.x] = t;
    }
}

// ---------------------------------------------------------------------------
__global__ void vq_final(float* __restrict__ out, int nblocks, int loss_pos) {
    __shared__ float sm[8];
    int tid = threadIdx.x;
    float s = 0.f;
    for (int i = tid; i < nblocks; i += 256) s += g_partial[i];
#pragma unroll
    for (int o = 16; o > 0; o >>= 1)
        s += __shfl_xor_sync(0xFFFFFFFFu, s, o);
    if ((tid & 31) == 0) sm[tid >> 5] = s;
    __syncthreads();
    if (tid == 0) {
        float t = 0.f;
        for (int i = 0; i < 8; ++i) t += sm[i];
        out[loss_pos] = t * (1.25f / (float)(F_ * B_ * D_));
    }
}

// ---------------------------------------------------------------------------
extern "C" void kernel_launch(void* const* d_in, const int* in_sizes, int n_in,
                              void* d_out, int out_size) {
    const float* x = (const float*)d_in[0];   // (F,B,D)
    const float* w = (const float*)d_in[1];   // (F,D,K)
    float* out = (float*)d_out;

    cudaFuncSetAttribute(vq_main, cudaFuncAttributeMaxDynamicSharedMemorySize,
                         SMEM_BYTES);

    dim3 pgrid(8, 32);
    vq_prep<<<pgrid, 256>>>(w);

    dim3 grid(B_ / 128, F_);
    vq_main<<<grid, NTHREADS, SMEM_BYTES>>>(x, out);

    vq_final<<<1, 256>>>(out, 1024, out_size - 1);
}

// round 6
// speedup vs baseline: 2.1813x; 1.2627x over previous
#include <cuda_runtime.h>
#include <cuda_fp16.h>
#include <cstdint>

#define F_ 32
#define B_ 4096
#define D_ 64
#define K_ 512
#define NTHREADS 256

// ---------------- device scratch ----------------
__device__ __half g_wh1[(size_t)F_ * K_ * D_];  // fp16 limb1, [f][k][d]
__device__ __half g_wh2[(size_t)F_ * K_ * D_];  // fp16 limb2, [f][k][d]
__device__ float  g_wn [F_ * K_];               // 0.5*||w_k||^2
__device__ float  g_partial[1024];
__device__ int    g_count;                      // zero-initialized, reset each run

__device__ __forceinline__ uint32_t smem_u32(const void* p) {
    uint32_t a;
    asm("{ .reg .u64 t; cvta.to.shared.u64 t, %1; cvt.u32.u64 %0, t; }"
        : "=r"(a) : "l"(p));
    return a;
}

#define LDSM_X4(r_, addr_) \
    asm volatile("ldmatrix.sync.aligned.m8n8.x4.shared.b16 {%0,%1,%2,%3}, [%4];" \
        : "=r"((r_)[0]), "=r"((r_)[1]), "=r"((r_)[2]), "=r"((r_)[3]) : "r"(addr_))

#define CP_ASYNC16(dst_, src_) \
    asm volatile("cp.async.cg.shared.global [%0], [%1], 16;" :: "r"(dst_), "l"(src_))
#define CP_COMMIT() asm volatile("cp.async.commit_group;" ::: "memory")
#define CP_WAIT0()  asm volatile("cp.async.wait_group 0;" ::: "memory")

__device__ __forceinline__ void mma_f16(float* c, const uint32_t* a,
                                        const uint32_t* b) {
    asm volatile(
        "mma.sync.aligned.m16n8k16.row.col.f32.f16.f16.f32 "
        "{%0,%1,%2,%3}, {%4,%5,%6,%7}, {%8,%9}, {%0,%1,%2,%3};"
        : "+f"(c[0]), "+f"(c[1]), "+f"(c[2]), "+f"(c[3])
        : "r"(a[0]), "r"(a[1]), "r"(a[2]), "r"(a[3]), "r"(b[0]), "r"(b[1]));
}

__device__ __forceinline__ uint32_t pack_h2(__half a, __half b) {
    __half2 h = __halves2half2(a, b);
    return *(uint32_t*)&h;
}

// smem layout (bytes). All tiles use 128B rows + SW128 XOR swizzle
// (phys = row*128 + (col ^ ((row&7)<<4))).
//   0      wns[512] f32 (2048)
//   2048   sidx[128] int (512)
//   2560   red8[8] f32 (32)
//   4096   xs limb1  128x128B (16384)
//   20480  xs limb2  (16384)
//   36864  ws: buf0 limb1 | buf0 limb2 | buf1 limb1 | buf1 limb2 (4x16384)
//          overlay after GEMM: red_v[2048] f32, red_i[2048] int
#define OFF_WNS  0
#define OFF_SIDX 2048
#define OFF_RED8 2560
#define OFF_X1   4096
#define OFF_X2   20480
#define OFF_WS   36864
#define SMEM_BYTES 102400

// ---------------------------------------------------------------------------
// Prep: transpose + fp16 2-limb split + norms. grid (16, 32) x 256.
// Block = (f = blockIdx.y, codes kt*32 .. +32)
// ---------------------------------------------------------------------------
__global__ void vq_prep(const float* __restrict__ w) {
    __shared__ float ts[32][65];
    const int f = blockIdx.y, kt = blockIdx.x, tid = threadIdx.x;
    const float* wf = w + (size_t)f * D_ * K_ + kt * 32;

    for (int i = tid; i < 64 * 32; i += 256) {
        int d = i >> 5, kk = i & 31;
        ts[kk][d] = wf[(size_t)d * K_ + kk];      // coalesced along k
    }
    __syncthreads();

    size_t base = ((size_t)f * K_ + (size_t)kt * 32) * D_;
    for (int i = tid; i < 32 * 64; i += 256) {
        int kk = i >> 6, d = i & 63;
        float v = ts[kk][d];
        __half h1 = __float2half_rn(v);
        __half h2 = __float2half_rn(v - __half2float(h1));
        g_wh1[base + i] = h1;
        g_wh2[base + i] = h2;
    }
    if (tid < 32) {
        float s = 0.f;
#pragma unroll
        for (int d = 0; d < 64; ++d) { float v = ts[tid][d]; s += v * v; }
        g_wn[f * K_ + kt * 32 + tid] = 0.5f * s;
    }
}

// ---------------------------------------------------------------------------
// Main: fp16 3-product mma.sync GEMM, cp.async double-buffered B,
// fused argmax + gather + loss, last-block final reduction.
// grid (32, 32): x = 128-row tile, y = f. 256 thr = 8 warps (2M x 4N).
// ---------------------------------------------------------------------------
__global__ __launch_bounds__(NTHREADS, 2)
void vq_main(const float* __restrict__ x, float* __restrict__ out,
             int loss_pos) {
    extern __shared__ __align__(1024) char smem[];
    const uint32_t sb = smem_u32(smem);
    float* wns  = (float*)(smem + OFF_WNS);
    int*   sidx = (int*)(smem + OFF_SIDX);
    float* red8 = (float*)(smem + OFF_RED8);
    float* red_v = (float*)(smem + OFF_WS);
    int*   red_i = (int*)(smem + OFF_WS + 8192);

    const int f   = blockIdx.y;
    const int b0  = blockIdx.x * 128;
    const int tid = threadIdx.x;
    const int wid = tid >> 5;
    const int lane = tid & 31;
    const int tq = lane >> 2, tr = lane & 3;
    const int wm = wid >> 2,  wn = wid & 3;
    const int lq = lane & 7,  quad = lane >> 3;
    const uint32_t xorv = (uint32_t)lq << 4;

    const __half* wh1g = g_wh1 + ((size_t)f << 9) * D_;
    const __half* wh2g = g_wh2 + ((size_t)f << 9) * D_;

    // ---- prologue: cp.async chunk 0 into buf 0 ----
    {
#pragma unroll
        for (int t = 0; t < 8; ++t) {
            int i = tid + t * 256;              // [0,2048)
            int limb = i >> 10;
            int n    = (i >> 3) & 127;
            int ch   = i & 7;
            uint32_t dst = sb + OFF_WS + limb * 16384
                         + (uint32_t)n * 128
                         + (((uint32_t)ch * 16) ^ ((uint32_t)(n & 7) << 4));
            const __half* src = (limb ? wh2g : wh1g)
                              + ((size_t)n) * 64 + ch * 8;
            CP_ASYNC16(dst, src);
        }
        CP_COMMIT();
    }

    wns[tid]       = g_wn[(f << 9) + tid];
    wns[tid + 256] = g_wn[(f << 9) + tid + 256];

    // ---- x tile -> fp16 limbs, swizzled [row][d] 128B rows ----
    const float* xg = x + ((size_t)f * B_ + b0) * D_;
#pragma unroll
    for (int t = 0; t < 8; ++t) {
        int i = tid + t * 256;                  // [0,2048)
        int r = i >> 4, c4 = i & 15;
        float4 v = ((const float4*)(xg + (size_t)r * D_))[c4];
        __half h1[4], h2[4];
        float vv[4] = {v.x, v.y, v.z, v.w};
#pragma unroll
        for (int j = 0; j < 4; ++j) {
            h1[j] = __float2half_rn(vv[j]);
            h2[j] = __float2half_rn(vv[j] - __half2float(h1[j]));
        }
        uint32_t off = (uint32_t)r * 128
                     + (((uint32_t)c4 * 8) ^ ((uint32_t)(r & 7) << 4));
        *(uint2*)(smem + OFF_X1 + off) =
            make_uint2(pack_h2(h1[0], h1[1]), pack_h2(h1[2], h1[3]));
        *(uint2*)(smem + OFF_X2 + off) =
            make_uint2(pack_h2(h2[0], h2[1]), pack_h2(h2[2], h2[3]));
    }

    float best[8];
    int   bidx[8];
#pragma unroll
    for (int i = 0; i < 8; ++i) { best[i] = -1e30f; bidx[i] = 0; }

    const uint32_t aBase = sb + OFF_X1
        + (uint32_t)(wm * 64 + lq + ((quad & 1) << 3)) * 128;
    const uint32_t aColBase = (uint32_t)((quad >> 1) << 4);
    const uint32_t bRowOff = (uint32_t)(wn * 32 + lq) * 128;
    const uint32_t bColBase = (uint32_t)quad * 16;

    for (int c = 0; c < 4; ++c) {
        CP_WAIT0();
        __syncthreads();     // buf (c&1) ready; prior readers of other buf done

        if (c < 3) {         // prefetch chunk c+1 into alternate buffer
            int cn = c + 1;
            uint32_t bufoff = (uint32_t)(cn & 1) * 32768;
#pragma unroll
            for (int t = 0; t < 8; ++t) {
                int i = tid + t * 256;
                int limb = i >> 10;
                int n    = (i >> 3) & 127;
                int ch   = i & 7;
                uint32_t dst = sb + OFF_WS + bufoff + limb * 16384
                             + (uint32_t)n * 128
                             + (((uint32_t)ch * 16) ^ ((uint32_t)(n & 7) << 4));
                const __half* src = (limb ? wh2g : wh1g)
                                  + ((size_t)(cn * 128 + n)) * 64 + ch * 8;
                CP_ASYNC16(dst, src);
            }
            CP_COMMIT();
        }

        const uint32_t wsb = sb + OFF_WS + (uint32_t)(c & 1) * 32768;

        float acc[4][4][4];
#pragma unroll
        for (int i = 0; i < 4; ++i)
#pragma unroll
            for (int j = 0; j < 4; ++j)
#pragma unroll
                for (int q = 0; q < 4; ++q) acc[i][j][q] = 0.f;

#pragma unroll
        for (int kkp = 0; kkp < 2; ++kkp) {
            uint32_t bb1[4][4], bb2[4][4];
#pragma unroll
            for (int j = 0; j < 4; ++j) {
                uint32_t ba = wsb + bRowOff + (uint32_t)j * 1024
                            + ((bColBase + (uint32_t)kkp * 64) ^ xorv);
                LDSM_X4(bb1[j], ba);
                LDSM_X4(bb2[j], ba + 16384);
            }
#pragma unroll
            for (int kk2 = 0; kk2 < 2; ++kk2) {
                const int kreg = kk2 * 2;
                const uint32_t kcol = (uint32_t)(kkp * 2 + kk2) * 32;
#pragma unroll
                for (int i = 0; i < 4; ++i) {
                    uint32_t aa = aBase + (uint32_t)i * 2048
                                + ((aColBase + kcol) ^ xorv);
                    uint32_t a1[4], a2[4];
                    LDSM_X4(a1, aa);
                    LDSM_X4(a2, aa + 16384);
#pragma unroll
                    for (int j = 0; j < 4; ++j) {
                        mma_f16(acc[i][j], a1, &bb1[j][kreg]);  // h1*w1
                        mma_f16(acc[i][j], a1, &bb2[j][kreg]);  // h1*w2
                        mma_f16(acc[i][j], a2, &bb1[j][kreg]);  // h2*w1
                    }
                }
            }
        }

        // fold scores into running argmax (k ascending; strict >)
#pragma unroll
        for (int j = 0; j < 4; ++j)
#pragma unroll
            for (int c01 = 0; c01 < 2; ++c01) {
                int kg = c * 128 + wn * 32 + j * 8 + tr * 2 + c01;
                float wnv = wns[kg];
#pragma unroll
                for (int i = 0; i < 4; ++i)
#pragma unroll
                    for (int h = 0; h < 2; ++h) {
                        float s = acc[i][j][h * 2 + c01] - wnv;
                        int slot = i * 2 + h;
                        if (s > best[slot]) { best[slot] = s; bidx[slot] = kg; }
                    }
            }
    }

    __syncthreads();   // all ws reads done; overlay reduction arrays

#pragma unroll
    for (int i = 0; i < 4; ++i)
#pragma unroll
        for (int h = 0; h < 2; ++h) {
            int row = wm * 64 + i * 16 + h * 8 + tq;
            red_v[row * 16 + wn * 4 + tr] = best[i * 2 + h];
            red_i[row * 16 + wn * 4 + tr] = bidx[i * 2 + h];
        }
    __syncthreads();

    if (tid < 128) {
        float bv = -1e30f;
        int bk = 0x7FFFFFFF;
#pragma unroll
        for (int t = 0; t < 16; ++t) {
            float v = red_v[tid * 16 + t];
            int  kk = red_i[tid * 16 + t];
            if (v > bv || (v == bv && kk < bk)) { bv = v; bk = kk; }
        }
        sidx[tid] = bk;
    }
    __syncthreads();

    // ---- gather (q = h1 + h2) + loss ----
    float lsum = 0.f;
    float* og = out + ((size_t)f * B_ + b0) * D_;
    for (int e = tid; e < 128 * D_; e += NTHREADS) {
        int r = e >> 6, d = e & 63;
        size_t gi = (size_t)sidx[r] * D_ + d;
        float q  = __half2float(wh1g[gi]) + __half2float(wh2g[gi]);
        float xv = xg[e];
        og[e] = q;
        float dif = q - xv;
        lsum += dif * dif;
    }
#pragma unroll
    for (int o = 16; o > 0; o >>= 1)
        lsum += __shfl_xor_sync(0xFFFFFFFFu, lsum, o);
    if ((tid & 31) == 0) red8[wid] = lsum;
    __syncthreads();

    __shared__ int s_last;
    if (tid == 0) {
        float t = 0.f;
#pragma unroll
        for (int i = 0; i < 8; ++i) t += red8[i];
        g_partial[blockIdx.y * gridDim.x + blockIdx.x] = t;
        __threadfence();
        int old = atomicAdd(&g_count, 1);
        s_last = (old == 1023) ? 1 : 0;
    }
    __syncthreads();

    // ---- last block: deterministic final loss reduction ----
    if (s_last) {
        float s = 0.f;
#pragma unroll
        for (int t = 0; t < 4; ++t) s += g_partial[tid + t * 256];
#pragma unroll
        for (int o = 16; o > 0; o >>= 1)
            s += __shfl_xor_sync(0xFFFFFFFFu, s, o);
        if ((tid & 31) == 0) red8[wid] = s;
        __syncthreads();
        if (tid == 0) {
            float t = 0.f;
#pragma unroll
            for (int i = 0; i < 8; ++i) t += red8[i];
            out[loss_pos] = t * (1.25f / (float)(F_ * B_ * D_));
            g_count = 0;   // reset for next graph replay
        }
    }
}

// ---------------------------------------------------------------------------
extern "C" void kernel_launch(void* const* d_in, const int* in_sizes, int n_in,
                              void* d_out, int out_size) {
    const float* x = (const float*)d_in[0];   // (F,B,D)
    const float* w = (const float*)d_in[1];   // (F,D,K)
    float* out = (float*)d_out;

    cudaFuncSetAttribute(vq_main, cudaFuncAttributeMaxDynamicSharedMemorySize,
                         SMEM_BYTES);

    dim3 pgrid(16, 32);
    vq_prep<<<pgrid, 256>>>(w);

    dim3 grid(B_ / 128, F_);
    vq_main<<<grid, NTHREADS, SMEM_BYTES>>>(x, out, out_size - 1);
}

// round 7
// speedup vs baseline: 2.2952x; 1.0522x over previous
#include <cuda_runtime.h>
#include <cuda_fp16.h>
#include <cstdint>

#define F_ 32
#define B_ 4096
#define D_ 64
#define K_ 512
#define NTHREADS 256

// ---------------- device scratch ----------------
__device__ __half g_wh1[(size_t)F_ * K_ * D_];  // fp16 limb1, [f][k][d]
__device__ __half g_wh2[(size_t)F_ * K_ * D_];  // fp16 limb2, [f][k][d]
__device__ float  g_wn [F_ * K_];               // 0.5*||w_k||^2
__device__ float  g_partial[1024];
__device__ int    g_count;

__device__ __forceinline__ uint32_t smem_u32(const void* p) {
    uint32_t a;
    asm("{ .reg .u64 t; cvta.to.shared.u64 t, %1; cvt.u32.u64 %0, t; }"
        : "=r"(a) : "l"(p));
    return a;
}

#define LDSM_X4(r_, addr_) \
    asm volatile("ldmatrix.sync.aligned.m8n8.x4.shared.b16 {%0,%1,%2,%3}, [%4];" \
        : "=r"((r_)[0]), "=r"((r_)[1]), "=r"((r_)[2]), "=r"((r_)[3]) : "r"(addr_))

#define CP_ASYNC16(dst_, src_) \
    asm volatile("cp.async.cg.shared.global [%0], [%1], 16;" :: "r"(dst_), "l"(src_))
#define CP_COMMIT() asm volatile("cp.async.commit_group;" ::: "memory")
#define CP_WAIT0()  asm volatile("cp.async.wait_group 0;" ::: "memory")

__device__ __forceinline__ void mma_f16(float* c, const uint32_t* a,
                                        const uint32_t* b) {
    asm volatile(
        "mma.sync.aligned.m16n8k16.row.col.f32.f16.f16.f32 "
        "{%0,%1,%2,%3}, {%4,%5,%6,%7}, {%8,%9}, {%0,%1,%2,%3};"
        : "+f"(c[0]), "+f"(c[1]), "+f"(c[2]), "+f"(c[3])
        : "r"(a[0]), "r"(a[1]), "r"(a[2]), "r"(a[3]), "r"(b[0]), "r"(b[1]));
}

__device__ __forceinline__ uint32_t pack_h2(__half a, __half b) {
    __half2 h = __halves2half2(a, b);
    return *(uint32_t*)&h;
}

// smem (bytes). 128B rows + SW128 XOR swizzle: phys = row*128 + (col ^ ((row&7)<<4))
//   0      wns[512] f32 (2048)
//   2048   sidx[128] int (512)
//   2560   red8[8] f32 (32)
//   4096   xs limb1 128x128B (16384)
//   20480  xs limb2 (16384)
//   36864  ws: buf0{limb1 8K, limb2 8K}, buf1{limb1 8K, limb2 8K} (32768)
//          overlay after GEMM: red_v[2048] f32 @36864, red_i[2048] int @45056
#define OFF_WNS  0
#define OFF_SIDX 2048
#define OFF_RED8 2560
#define OFF_X1   4096
#define OFF_X2   20480
#define OFF_WS   36864
#define SMEM_BYTES 69632

// ---------------------------------------------------------------------------
// Prep: transpose + fp16 2-limb split + norms. grid (16, 32) x 256.
// ---------------------------------------------------------------------------
__global__ void vq_prep(const float* __restrict__ w) {
    __shared__ float ts[32][65];
    const int f = blockIdx.y, kt = blockIdx.x, tid = threadIdx.x;
    const float* wf = w + (size_t)f * D_ * K_ + kt * 32;

    for (int i = tid; i < 64 * 32; i += 256) {
        int d = i >> 5, kk = i & 31;
        ts[kk][d] = wf[(size_t)d * K_ + kk];
    }
    __syncthreads();

    size_t base = ((size_t)f * K_ + (size_t)kt * 32) * D_;
    for (int i = tid; i < 32 * 64; i += 256) {
        int kk = i >> 6, d = i & 63;
        float v = ts[kk][d];
        __half h1 = __float2half_rn(v);
        __half h2 = __float2half_rn(v - __half2float(h1));
        g_wh1[base + i] = h1;
        g_wh2[base + i] = h2;
    }
    if (tid < 32) {
        float s = 0.f;
#pragma unroll
        for (int d = 0; d < 64; ++d) { float v = ts[tid][d]; s += v * v; }
        g_wn[f * K_ + kt * 32 + tid] = 0.5f * s;
    }
}

// ---------------------------------------------------------------------------
// Main: fp16 3-product mma.sync, 8x 64-code chunks (cp.async double-buffered),
// warp tile 64x16 (2M x 4N), 3 CTAs/SM target. Fused argmax+gather+loss.
// ---------------------------------------------------------------------------
__global__ __launch_bounds__(NTHREADS, 3)
void vq_main(const float* __restrict__ x, float* __restrict__ out,
             int loss_pos) {
    extern __shared__ __align__(1024) char smem[];
    const uint32_t sb = smem_u32(smem);
    float* wns  = (float*)(smem + OFF_WNS);
    int*   sidx = (int*)(smem + OFF_SIDX);
    float* red8 = (float*)(smem + OFF_RED8);
    float* red_v = (float*)(smem + OFF_WS);
    int*   red_i = (int*)(smem + OFF_WS + 8192);

    const int f   = blockIdx.y;
    const int b0  = blockIdx.x * 128;
    const int tid = threadIdx.x;
    const int wid = tid >> 5;
    const int lane = tid & 31;
    const int tq = lane >> 2, tr = lane & 3;
    const int wm = wid >> 2,  wn = wid & 3;
    const int lq = lane & 7,  quad = lane >> 3;
    const uint32_t xorv = (uint32_t)lq << 4;

    const __half* wh1g = g_wh1 + ((size_t)f << 9) * D_;
    const __half* wh2g = g_wh2 + ((size_t)f << 9) * D_;

    // ---- prologue: cp.async chunk 0 (codes 0..63) into buf 0 ----
    {
#pragma unroll
        for (int t = 0; t < 4; ++t) {
            int i = tid + t * 256;              // [0,1024)
            int limb = i >> 9;
            int n    = (i >> 3) & 63;
            int ch   = i & 7;
            uint32_t dst = sb + OFF_WS + (uint32_t)limb * 8192
                         + (uint32_t)n * 128
                         + (((uint32_t)ch * 16) ^ ((uint32_t)(n & 7) << 4));
            const __half* src = (limb ? wh2g : wh1g) + (size_t)n * 64 + ch * 8;
            CP_ASYNC16(dst, src);
        }
        CP_COMMIT();
    }

    wns[tid]       = g_wn[(f << 9) + tid];
    wns[tid + 256] = g_wn[(f << 9) + tid + 256];

    // ---- x tile -> fp16 limbs, swizzled 128B rows ----
    const float* xg = x + ((size_t)f * B_ + b0) * D_;
#pragma unroll
    for (int t = 0; t < 8; ++t) {
        int i = tid + t * 256;                  // [0,2048)
        int r = i >> 4, c4 = i & 15;
        float4 v = ((const float4*)(xg + (size_t)r * D_))[c4];
        __half h1[4], h2[4];
        float vv[4] = {v.x, v.y, v.z, v.w};
#pragma unroll
        for (int j = 0; j < 4; ++j) {
            h1[j] = __float2half_rn(vv[j]);
            h2[j] = __float2half_rn(vv[j] - __half2float(h1[j]));
        }
        uint32_t off = (uint32_t)r * 128
                     + (((uint32_t)c4 * 8) ^ ((uint32_t)(r & 7) << 4));
        *(uint2*)(smem + OFF_X1 + off) =
            make_uint2(pack_h2(h1[0], h1[1]), pack_h2(h1[2], h1[3]));
        *(uint2*)(smem + OFF_X2 + off) =
            make_uint2(pack_h2(h2[0], h2[1]), pack_h2(h2[2], h2[3]));
    }

    float best[8];
    int   bidx[8];
#pragma unroll
    for (int i = 0; i < 8; ++i) { best[i] = -1e30f; bidx[i] = 0; }

    const uint32_t aBase = sb + OFF_X1
        + (uint32_t)(wm * 64 + lq + ((quad & 1) << 3)) * 128;
    const uint32_t aColBase = (uint32_t)((quad >> 1) << 4);
    const uint32_t bRowOff = (uint32_t)(wn * 16 + lq) * 128;
    const uint32_t bColBase = (uint32_t)quad * 16;

    for (int c = 0; c < 8; ++c) {
        CP_WAIT0();
        __syncthreads();     // buf (c&1) ready; prior readers of other buf done

        if (c < 7) {         // prefetch chunk c+1
            int cn = c + 1;
            uint32_t bufoff = (uint32_t)(cn & 1) * 16384;
#pragma unroll
            for (int t = 0; t < 4; ++t) {
                int i = tid + t * 256;
                int limb = i >> 9;
                int n    = (i >> 3) & 63;
                int ch   = i & 7;
                uint32_t dst = sb + OFF_WS + bufoff + (uint32_t)limb * 8192
                             + (uint32_t)n * 128
                             + (((uint32_t)ch * 16) ^ ((uint32_t)(n & 7) << 4));
                const __half* src = (limb ? wh2g : wh1g)
                                  + ((size_t)(cn * 64 + n)) * 64 + ch * 8;
                CP_ASYNC16(dst, src);
            }
            CP_COMMIT();
        }

        const uint32_t wsb = sb + OFF_WS + (uint32_t)(c & 1) * 16384;

        float acc[4][2][4];
#pragma unroll
        for (int i = 0; i < 4; ++i)
#pragma unroll
            for (int j = 0; j < 2; ++j)
#pragma unroll
                for (int q = 0; q < 4; ++q) acc[i][j][q] = 0.f;

#pragma unroll
        for (int kkp = 0; kkp < 2; ++kkp) {
            uint32_t bb1[2][4], bb2[2][4];
#pragma unroll
            for (int j = 0; j < 2; ++j) {
                uint32_t ba = wsb + bRowOff + (uint32_t)j * 1024
                            + ((bColBase + (uint32_t)kkp * 64) ^ xorv);
                LDSM_X4(bb1[j], ba);
                LDSM_X4(bb2[j], ba + 8192);
            }
#pragma unroll
            for (int kk2 = 0; kk2 < 2; ++kk2) {
                const int kreg = kk2 * 2;
                const uint32_t kcol = (uint32_t)(kkp * 2 + kk2) * 32;
#pragma unroll
                for (int i = 0; i < 4; ++i) {
                    uint32_t aa = aBase + (uint32_t)i * 2048
                                + ((aColBase + kcol) ^ xorv);
                    uint32_t a1[4], a2[4];
                    LDSM_X4(a1, aa);
                    LDSM_X4(a2, aa + 16384);
#pragma unroll
                    for (int j = 0; j < 2; ++j) {
                        mma_f16(acc[i][j], a1, &bb1[j][kreg]);  // h1*w1
                        mma_f16(acc[i][j], a1, &bb2[j][kreg]);  // h1*w2
                        mma_f16(acc[i][j], a2, &bb1[j][kreg]);  // h2*w1
                    }
                }
            }
        }

        // fold chunk scores into running argmax (k ascending; strict >)
#pragma unroll
        for (int j = 0; j < 2; ++j)
#pragma unroll
            for (int c01 = 0; c01 < 2; ++c01) {
                int kg = c * 64 + wn * 16 + j * 8 + tr * 2 + c01;
                float wnv = wns[kg];
#pragma unroll
                for (int i = 0; i < 4; ++i)
#pragma unroll
                    for (int h = 0; h < 2; ++h) {
                        float s = acc[i][j][h * 2 + c01] - wnv;
                        int slot = i * 2 + h;
                        if (s > best[slot]) { best[slot] = s; bidx[slot] = kg; }
                    }
            }
    }

    __syncthreads();   // all ws reads done; overlay reduction arrays

#pragma unroll
    for (int i = 0; i < 4; ++i)
#pragma unroll
        for (int h = 0; h < 2; ++h) {
            int row = wm * 64 + i * 16 + h * 8 + tq;
            red_v[row * 16 + wn * 4 + tr] = best[i * 2 + h];
            red_i[row * 16 + wn * 4 + tr] = bidx[i * 2 + h];
        }
    __syncthreads();

    if (tid < 128) {
        float bv = -1e30f;
        int bk = 0x7FFFFFFF;
#pragma unroll
        for (int t = 0; t < 16; ++t) {
            float v = red_v[tid * 16 + t];
            int  kk = red_i[tid * 16 + t];
            if (v > bv || (v == bv && kk < bk)) { bv = v; bk = kk; }
        }
        sidx[tid] = bk;
    }
    __syncthreads();

    // ---- gather (q = h1 + h2) + loss ----
    float lsum = 0.f;
    float* og = out + ((size_t)f * B_ + b0) * D_;
    for (int e = tid; e < 128 * D_; e += NTHREADS) {
        int r = e >> 6, d = e & 63;
        size_t gi = (size_t)sidx[r] * D_ + d;
        float q  = __half2float(wh1g[gi]) + __half2float(wh2g[gi]);
        float xv = xg[e];
        og[e] = q;
        float dif = q - xv;
        lsum += dif * dif;
    }
#pragma unroll
    for (int o = 16; o > 0; o >>= 1)
        lsum += __shfl_xor_sync(0xFFFFFFFFu, lsum, o);
    if ((tid & 31) == 0) red8[wid] = lsum;
    __syncthreads();

    __shared__ int s_last;
    if (tid == 0) {
        float t = 0.f;
#pragma unroll
        for (int i = 0; i < 8; ++i) t += red8[i];
        g_partial[blockIdx.y * gridDim.x + blockIdx.x] = t;
        __threadfence();
        int old = atomicAdd(&g_count, 1);
        s_last = (old == 1023) ? 1 : 0;
    }
    __syncthreads();

    if (s_last) {
        float s = 0.f;
#pragma unroll
        for (int t = 0; t < 4; ++t) s += g_partial[tid + t * 256];
#pragma unroll
        for (int o = 16; o > 0; o >>= 1)
            s += __shfl_xor_sync(0xFFFFFFFFu, s, o);
        if ((tid & 31) == 0) red8[wid] = s;
        __syncthreads();
        if (tid == 0) {
            float t = 0.f;
#pragma unroll
            for (int i = 0; i < 8; ++i) t += red8[i];
            out[loss_pos] = t * (1.25f / (float)(F_ * B_ * D_));
            g_count = 0;
        }
    }
}

// ---------------------------------------------------------------------------
extern "C" void kernel_launch(void* const* d_in, const int* in_sizes, int n_in,
                              void* d_out, int out_size) {
    const float* x = (const float*)d_in[0];   // (F,B,D)
    const float* w = (const float*)d_in[1];   // (F,D,K)
    float* out = (float*)d_out;

    cudaFuncSetAttribute(vq_main, cudaFuncAttributeMaxDynamicSharedMemorySize,
                         SMEM_BYTES);

    dim3 pgrid(16, 32);
    vq_prep<<<pgrid, 256>>>(w);

    dim3 grid(B_ / 128, F_);
    vq_main<<<grid, NTHREADS, SMEM_BYTES>>>(x, out, out_size - 1);
}

// round 8
// speedup vs baseline: 2.3284x; 1.0145x over previous
#include <cuda_runtime.h>
#include <cuda_fp16.h>
#include <cstdint>

#define F_ 32
#define B_ 4096
#define D_ 64
#define K_ 512
#define NTHREADS 256

// ---------------- device scratch ----------------
__device__ __half g_wh1[(size_t)F_ * K_ * D_];  // fp16 limb1, [f][k][d]
__device__ __half g_wh2[(size_t)F_ * K_ * D_];  // fp16 limb2, [f][k][d]
__device__ float  g_wn [F_ * K_];               // 0.5*||w_k||^2
__device__ float  g_partial[1024];
__device__ int    g_count;

__device__ __forceinline__ uint32_t smem_u32(const void* p) {
    uint32_t a;
    asm("{ .reg .u64 t; cvta.to.shared.u64 t, %1; cvt.u32.u64 %0, t; }"
        : "=r"(a) : "l"(p));
    return a;
}

#define LDSM_X4(r_, addr_) \
    asm volatile("ldmatrix.sync.aligned.m8n8.x4.shared.b16 {%0,%1,%2,%3}, [%4];" \
        : "=r"((r_)[0]), "=r"((r_)[1]), "=r"((r_)[2]), "=r"((r_)[3]) : "r"(addr_))

#define CP_ASYNC16(dst_, src_) \
    asm volatile("cp.async.cg.shared.global [%0], [%1], 16;" :: "r"(dst_), "l"(src_))
#define CP_COMMIT() asm volatile("cp.async.commit_group;" ::: "memory")
#define CP_WAIT0()  asm volatile("cp.async.wait_group 0;" ::: "memory")

__device__ __forceinline__ void mma_f16(float* c, const uint32_t* a,
                                        const uint32_t* b) {
    asm volatile(
        "mma.sync.aligned.m16n8k16.row.col.f32.f16.f16.f32 "
        "{%0,%1,%2,%3}, {%4,%5,%6,%7}, {%8,%9}, {%0,%1,%2,%3};"
        : "+f"(c[0]), "+f"(c[1]), "+f"(c[2]), "+f"(c[3])
        : "r"(a[0]), "r"(a[1]), "r"(a[2]), "r"(a[3]), "r"(b[0]), "r"(b[1]));
}

__device__ __forceinline__ uint32_t pack_h2(__half a, __half b) {
    __half2 h = __halves2half2(a, b);
    return *(uint32_t*)&h;
}

// smem (bytes). 128B rows + SW128 XOR swizzle: phys = row*128 + (col ^ ((row&7)<<4))
#define OFF_WNS  0
#define OFF_SIDX 2048
#define OFF_RED8 2560
#define OFF_X1   4096
#define OFF_X2   20480
#define OFF_WS   36864
#define SMEM_BYTES 69632

// ---------------------------------------------------------------------------
// Prep: transpose + fp16 2-limb split + norms. grid (16, 32) x 256.
// ---------------------------------------------------------------------------
__global__ void vq_prep(const float* __restrict__ w) {
    __shared__ float ts[32][65];
    __shared__ float ps[32][9];
    const int f = blockIdx.y, kt = blockIdx.x, tid = threadIdx.x;
    const float* wf = w + (size_t)f * D_ * K_ + kt * 32;

    for (int i = tid; i < 64 * 32; i += 256) {
        int d = i >> 5, kk = i & 31;
        ts[kk][d] = wf[(size_t)d * K_ + kk];
    }
    __syncthreads();

    size_t base = ((size_t)f * K_ + (size_t)kt * 32) * D_;
    for (int i = tid; i < 32 * 64; i += 256) {
        int kk = i >> 6, d = i & 63;
        float v = ts[kk][d];
        __half h1 = __float2half_rn(v);
        __half h2 = __float2half_rn(v - __half2float(h1));
        g_wh1[base + i] = h1;
        g_wh2[base + i] = h2;
    }
    // norms: 8 threads per code, each sums 8 d's
    {
        int kk = tid >> 3, seg = tid & 7;
        float s = 0.f;
#pragma unroll
        for (int d8 = 0; d8 < 8; ++d8) {
            float v = ts[kk][seg * 8 + d8];
            s += v * v;
        }
        ps[kk][seg] = s;
    }
    __syncthreads();
    if (tid < 32) {
        float s = 0.f;
#pragma unroll
        for (int g = 0; g < 8; ++g) s += ps[tid][g];
        g_wn[f * K_ + kt * 32 + tid] = 0.5f * s;
    }
}

// ---------------------------------------------------------------------------
// Main: fp16 3-product mma.sync, product-grouped MMA issue (8-indep chains),
// cp.async double-buffered 64-code chunks, fused argmax+gather+loss.
// ---------------------------------------------------------------------------
__global__ __launch_bounds__(NTHREADS, 3)
void vq_main(const float* __restrict__ x, float* __restrict__ out,
             int loss_pos) {
    extern __shared__ __align__(1024) char smem[];
    const uint32_t sb = smem_u32(smem);
    float* wns  = (float*)(smem + OFF_WNS);
    int*   sidx = (int*)(smem + OFF_SIDX);
    float* red8 = (float*)(smem + OFF_RED8);
    float* red_v = (float*)(smem + OFF_WS);
    int*   red_i = (int*)(smem + OFF_WS + 8192);

    const int f   = blockIdx.y;
    const int b0  = blockIdx.x * 128;
    const int tid = threadIdx.x;
    const int wid = tid >> 5;
    const int lane = tid & 31;
    const int tq = lane >> 2, tr = lane & 3;
    const int wm = wid >> 2,  wn = wid & 3;
    const int lq = lane & 7,  quad = lane >> 3;
    const uint32_t xorv = (uint32_t)lq << 4;

    const __half* wh1g = g_wh1 + ((size_t)f << 9) * D_;
    const __half* wh2g = g_wh2 + ((size_t)f << 9) * D_;

    // ---- prologue: cp.async chunk 0 (codes 0..63) into buf 0 ----
    {
#pragma unroll
        for (int t = 0; t < 4; ++t) {
            int i = tid + t * 256;              // [0,1024)
            int limb = i >> 9;
            int n    = (i >> 3) & 63;
            int ch   = i & 7;
            uint32_t dst = sb + OFF_WS + (uint32_t)limb * 8192
                         + (uint32_t)n * 128
                         + (((uint32_t)ch * 16) ^ ((uint32_t)(n & 7) << 4));
            const __half* src = (limb ? wh2g : wh1g) + (size_t)n * 64 + ch * 8;
            CP_ASYNC16(dst, src);
        }
        CP_COMMIT();
    }

    wns[tid]       = g_wn[(f << 9) + tid];
    wns[tid + 256] = g_wn[(f << 9) + tid + 256];

    // ---- x tile -> fp16 limbs, swizzled 128B rows ----
    const float* xg = x + ((size_t)f * B_ + b0) * D_;
#pragma unroll
    for (int t = 0; t < 8; ++t) {
        int i = tid + t * 256;                  // [0,2048)
        int r = i >> 4, c4 = i & 15;
        float4 v = ((const float4*)(xg + (size_t)r * D_))[c4];
        __half h1[4], h2[4];
        float vv[4] = {v.x, v.y, v.z, v.w};
#pragma unroll
        for (int j = 0; j < 4; ++j) {
            h1[j] = __float2half_rn(vv[j]);
            h2[j] = __float2half_rn(vv[j] - __half2float(h1[j]));
        }
        uint32_t off = (uint32_t)r * 128
                     + (((uint32_t)c4 * 8) ^ ((uint32_t)(r & 7) << 4));
        *(uint2*)(smem + OFF_X1 + off) =
            make_uint2(pack_h2(h1[0], h1[1]), pack_h2(h1[2], h1[3]));
        *(uint2*)(smem + OFF_X2 + off) =
            make_uint2(pack_h2(h2[0], h2[1]), pack_h2(h2[2], h2[3]));
    }

    float best[8];
    int   bidx[8];
#pragma unroll
    for (int i = 0; i < 8; ++i) { best[i] = -1e30f; bidx[i] = 0; }

    const uint32_t aBase = sb + OFF_X1
        + (uint32_t)(wm * 64 + lq + ((quad & 1) << 3)) * 128;
    const uint32_t aColBase = (uint32_t)((quad >> 1) << 4);
    const uint32_t bRowOff = (uint32_t)(wn * 16 + lq) * 128;
    const uint32_t bColBase = (uint32_t)quad * 16;

    for (int c = 0; c < 8; ++c) {
        CP_WAIT0();
        __syncthreads();

        if (c < 7) {         // prefetch chunk c+1
            int cn = c + 1;
            uint32_t bufoff = (uint32_t)(cn & 1) * 16384;
#pragma unroll
            for (int t = 0; t < 4; ++t) {
                int i = tid + t * 256;
                int limb = i >> 9;
                int n    = (i >> 3) & 63;
                int ch   = i & 7;
                uint32_t dst = sb + OFF_WS + bufoff + (uint32_t)limb * 8192
                             + (uint32_t)n * 128
                             + (((uint32_t)ch * 16) ^ ((uint32_t)(n & 7) << 4));
                const __half* src = (limb ? wh2g : wh1g)
                                  + ((size_t)(cn * 64 + n)) * 64 + ch * 8;
                CP_ASYNC16(dst, src);
            }
            CP_COMMIT();
        }

        const uint32_t wsb = sb + OFF_WS + (uint32_t)(c & 1) * 16384;

        float acc[4][2][4];
#pragma unroll
        for (int i = 0; i < 4; ++i)
#pragma unroll
            for (int j = 0; j < 2; ++j)
#pragma unroll
                for (int q = 0; q < 4; ++q) acc[i][j][q] = 0.f;

#pragma unroll
        for (int kkp = 0; kkp < 2; ++kkp) {
            uint32_t bb1[2][4], bb2[2][4];
#pragma unroll
            for (int j = 0; j < 2; ++j) {
                uint32_t ba = wsb + bRowOff + (uint32_t)j * 1024
                            + ((bColBase + (uint32_t)kkp * 64) ^ xorv);
                LDSM_X4(bb1[j], ba);
                LDSM_X4(bb2[j], ba + 8192);
            }
#pragma unroll
            for (int kk2 = 0; kk2 < 2; ++kk2) {
                const int kreg = kk2 * 2;
                const uint32_t kcol = (uint32_t)(kkp * 2 + kk2) * 32;
                // load ALL A fragments (both limbs) up front
                uint32_t a1[4][4], a2[4][4];
#pragma unroll
                for (int i = 0; i < 4; ++i) {
                    uint32_t aa = aBase + (uint32_t)i * 2048
                                + ((aColBase + kcol) ^ xorv);
                    LDSM_X4(a1[i], aa);
                    LDSM_X4(a2[i], aa + 16384);
                }
                // product-grouped issue: 8 independent MMAs per group
#pragma unroll
                for (int i = 0; i < 4; ++i)
#pragma unroll
                    for (int j = 0; j < 2; ++j)
                        mma_f16(acc[i][j], a1[i], &bb1[j][kreg]);  // h1*w1
#pragma unroll
                for (int i = 0; i < 4; ++i)
#pragma unroll
                    for (int j = 0; j < 2; ++j)
                        mma_f16(acc[i][j], a1[i], &bb2[j][kreg]);  // h1*w2
#pragma unroll
                for (int i = 0; i < 4; ++i)
#pragma unroll
                    for (int j = 0; j < 2; ++j)
                        mma_f16(acc[i][j], a2[i], &bb1[j][kreg]);  // h2*w1
            }
        }

        // fold chunk scores into running argmax (k ascending; strict >)
#pragma unroll
        for (int j = 0; j < 2; ++j)
#pragma unroll
            for (int c01 = 0; c01 < 2; ++c01) {
                int kg = c * 64 + wn * 16 + j * 8 + tr * 2 + c01;
                float wnv = wns[kg];
#pragma unroll
                for (int i = 0; i < 4; ++i)
#pragma unroll
                    for (int h = 0; h < 2; ++h) {
                        float s = acc[i][j][h * 2 + c01] - wnv;
                        int slot = i * 2 + h;
                        if (s > best[slot]) { best[slot] = s; bidx[slot] = kg; }
                    }
            }
    }

    __syncthreads();   // all ws reads done; overlay reduction arrays

#pragma unroll
    for (int i = 0; i < 4; ++i)
#pragma unroll
        for (int h = 0; h < 2; ++h) {
            int row = wm * 64 + i * 16 + h * 8 + tq;
            red_v[row * 16 + wn * 4 + tr] = best[i * 2 + h];
            red_i[row * 16 + wn * 4 + tr] = bidx[i * 2 + h];
        }
    __syncthreads();

    if (tid < 128) {
        float bv = -1e30f;
        int bk = 0x7FFFFFFF;
#pragma unroll
        for (int t = 0; t < 16; ++t) {
            float v = red_v[tid * 16 + t];
            int  kk = red_i[tid * 16 + t];
            if (v > bv || (v == bv && kk < bk)) { bv = v; bk = kk; }
        }
        sidx[tid] = bk;
    }
    __syncthreads();

    // ---- gather (q = h1 + h2) + loss ----
    float lsum = 0.f;
    float* og = out + ((size_t)f * B_ + b0) * D_;
    for (int e = tid; e < 128 * D_; e += NTHREADS) {
        int r = e >> 6, d = e & 63;
        size_t gi = (size_t)sidx[r] * D_ + d;
        float q  = __half2float(wh1g[gi]) + __half2float(wh2g[gi]);
        float xv = xg[e];
        og[e] = q;
        float dif = q - xv;
        lsum += dif * dif;
    }
#pragma unroll
    for (int o = 16; o > 0; o >>= 1)
        lsum += __shfl_xor_sync(0xFFFFFFFFu, lsum, o);
    if ((tid & 31) == 0) red8[wid] = lsum;
    __syncthreads();

    __shared__ int s_last;
    if (tid == 0) {
        float t = 0.f;
#pragma unroll
        for (int i = 0; i < 8; ++i) t += red8[i];
        g_partial[blockIdx.y * gridDim.x + blockIdx.x] = t;
        __threadfence();
        int old = atomicAdd(&g_count, 1);
        s_last = (old == 1023) ? 1 : 0;
    }
    __syncthreads();

    if (s_last) {
        float s = 0.f;
#pragma unroll
        for (int t = 0; t < 4; ++t) s += g_partial[tid + t * 256];
#pragma unroll
        for (int o = 16; o > 0; o >>= 1)
            s += __shfl_xor_sync(0xFFFFFFFFu, s, o);
        if ((tid & 31) == 0) red8[wid] = s;
        __syncthreads();
        if (tid == 0) {
            float t = 0.f;
#pragma unroll
            for (int i = 0; i < 8; ++i) t += red8[i];
            out[loss_pos] = t * (1.25f / (float)(F_ * B_ * D_));
            g_count = 0;
        }
    }
}

// ---------------------------------------------------------------------------
extern "C" void kernel_launch(void* const* d_in, const int* in_sizes, int n_in,
                              void* d_out, int out_size) {
    const float* x = (const float*)d_in[0];   // (F,B,D)
    const float* w = (const float*)d_in[1];   // (F,D,K)
    float* out = (float*)d_out;

    cudaFuncSetAttribute(vq_main, cudaFuncAttributeMaxDynamicSharedMemorySize,
                         SMEM_BYTES);

    dim3 pgrid(16, 32);
    vq_prep<<<pgrid, 256>>>(w);

    dim3 grid(B_ / 128, F_);
    vq_main<<<grid, NTHREADS, SMEM_BYTES>>>(x, out, out_size - 1);
}